// round 15
// baseline (speedup 1.0000x reference)
#include <cuda_runtime.h>
#include <cuda_fp16.h>
#include <math.h>
#include <stdint.h>

// ---------------------------------------------------------------------------
#define C_DIM   192
#define NH      6
#define NWIN    4096
#define M_TOT   262144
#define HIDDEN  768
#define QKV_N   576
#define SCALE_F 0.17677669529663687f

// ---------------------------------------------------------------------------
#define SZ_H16  ((size_t)M_TOT * HIDDEN * 2)
#define SZ_CD16 ((size_t)M_TOT * C_DIM * 2)
#define SZ_CD32 ((size_t)M_TOT * C_DIM * 4)
#define OFF_XA  (SZ_H16)
#define OFF_T   (OFF_XA + SZ_CD16)
#define OFF_X1F (OFF_T + SZ_CD32)
#define OFF_X1H (OFF_X1F + SZ_CD32)
#define POOLSZ  (OFF_X1H + SZ_CD16)

__device__ __align__(256) char g_pool[POOLSZ];

__device__ __half g_wq[QKV_N * C_DIM];
__device__ __half g_wp[C_DIM * C_DIM];
__device__ __half g_w1[HIDDEN * C_DIM];
__device__ __half g_w2[C_DIM * HIDDEN];
__device__ float  g_rpbd[NH * 64 * 64];

// ---------------------------------------------------------------------------
__device__ __forceinline__ int map_row(int m) {
    int w    = m >> 6;
    int t    = m & 63;
    int b    = w >> 10;
    int widx = w & 1023;
    int wh   = widx >> 5;
    int ww   = widx & 31;
    int r    = t >> 3;
    int c    = t & 7;
    int h    = (wh * 8 + r + 4) & 255;
    int wc   = (ww * 8 + c + 4) & 255;
    return (b << 16) | (h << 8) | wc;
}

__device__ __forceinline__ uint32_t smem_to_u32(const void* p) {
    uint32_t a;
    asm("{ .reg .u64 t; cvta.to.shared.u64 t, %1; cvt.u32.u64 %0, t; }" : "=r"(a) : "l"(p));
    return a;
}

#define CP_ASYNC16(dst, src) \
    asm volatile("cp.async.cg.shared.global [%0], [%1], 16;" :: "r"(dst), "l"(src))
#define CP_COMMIT() asm volatile("cp.async.commit_group;")
#define CP_WAIT(n)  asm volatile("cp.async.wait_group %0;" :: "n"(n))

#define LDM_X4(r0, r1, r2, r3, addr) \
    asm volatile("ldmatrix.sync.aligned.m8n8.x4.shared.b16 {%0,%1,%2,%3}, [%4];" \
                 : "=r"(r0), "=r"(r1), "=r"(r2), "=r"(r3) : "r"(addr))
#define LDM_X4_T(r0, r1, r2, r3, addr) \
    asm volatile("ldmatrix.sync.aligned.m8n8.x4.trans.shared.b16 {%0,%1,%2,%3}, [%4];" \
                 : "=r"(r0), "=r"(r1), "=r"(r2), "=r"(r3) : "r"(addr))

#define MMA_F16(d, a, b) \
    asm volatile("mma.sync.aligned.m16n8k16.row.col.f32.f16.f16.f32 " \
                 "{%0,%1,%2,%3}, {%4,%5,%6,%7}, {%8,%9}, {%0,%1,%2,%3};" \
                 : "+f"((d)[0]), "+f"((d)[1]), "+f"((d)[2]), "+f"((d)[3]) \
                 : "r"((a)[0]), "r"((a)[1]), "r"((a)[2]), "r"((a)[3]), \
                   "r"((b)[0]), "r"((b)[1]))

__device__ __forceinline__ uint32_t pk_h2(float x, float y) {
    __half2 t = __floats2half2_rn(x, y);
    return *(uint32_t*)&t;
}

// ---------------------------------------------------------------------------
// Prep kernels
// ---------------------------------------------------------------------------
__global__ __launch_bounds__(256) void prep_x(
    const float* __restrict__ x, uint32_t* __restrict__ xo)
{
    int idx = blockIdx.x * 256 + threadIdx.x;
    int m = idx / 48, c4 = idx % 48;
    float4 v = *(const float4*)(x + (size_t)map_row(m) * C_DIM + c4 * 4);
    *(uint2*)(xo + ((size_t)m * C_DIM + c4 * 4) / 2) =
        make_uint2(pk_h2(v.x, v.y), pk_h2(v.z, v.w));
}

__global__ __launch_bounds__(256) void prep_w(
    const float* __restrict__ w, uint32_t* __restrict__ wo, int K)
{
    int idx = blockIdx.x * 256 + threadIdx.x;
    int k4 = K / 4;
    int row = idx / k4, c4 = idx % k4;
    float4 v = *(const float4*)(w + (size_t)row * K + c4 * 4);
    *(uint2*)(wo + ((size_t)row * K + c4 * 4) / 2) =
        make_uint2(pk_h2(v.x, v.y), pk_h2(v.z, v.w));
}

__global__ void prep_rpb(const float* __restrict__ rpb_table, const int* __restrict__ rel_idx,
                         float* __restrict__ rpbd)
{
    int idx = blockIdx.x * 256 + threadIdx.x;
    int h = idx >> 12, tj = idx & 4095;
    rpbd[idx] = rpb_table[rel_idx[tj] * NH + h];
}

// ---------------------------------------------------------------------------
// Pipelined fp16 HMMA GEMM, high occupancy variant.
// BM=128, BN=64, BK=32, 3-stage cp.async, 256 thr, warps 4(M) x 2(N),
// warp tile 32x32 (acc 32 regs). __launch_bounds__(256,3) -> <=85 regs ->
// 3 CTA/SM = 24 warps (RF-fit), smem 46080/CTA x3 = 138KB.
// ---------------------------------------------------------------------------
#define BK   32
#define RS   80                 // 64B data + 16B pad
#define ATB  (128 * RS)         // 10240
#define BTB  (64 * RS)          // 5120
#define SSTG (ATB + BTB)        // 15360
#define NSTG 3
#define MMSMEM (NSTG * SSTG)    // 46080

template<bool SCATTER, bool DOGELU>
__global__ __launch_bounds__(256, 3) void mm_p3(
    const __half* __restrict__ A, const __half* __restrict__ W,
    const float* __restrict__ bias, uint32_t* __restrict__ Ou,
    float* __restrict__ Of, int N, int K)
{
    extern __shared__ char sm[];
    const uint32_t sbase = smem_to_u32(sm);

    const int tid = threadIdx.x, wid = tid >> 5, lane = tid & 31;
    const int warpM = wid & 3, warpN = wid >> 2;
    const int rowBase = blockIdx.y * 128;
    const int colBase = blockIdx.x * 64;
    const int nch = K / BK;

    // staging: A 512 chunks (2/thr), B 256 (1/thr); 4 chunks per row
    const int srow = tid >> 2, skc = tid & 3;
    const __half* aSrc0 = A + (size_t)(rowBase + srow) * K + skc * 8;
    const __half* aSrc1 = A + (size_t)(rowBase + 64 + srow) * K + skc * 8;
    const __half* bSrc0 = W + (size_t)(colBase + srow) * K + skc * 8;
    const uint32_t aDst0 = srow * RS + skc * 16;
    const uint32_t aDst1 = (64 + srow) * RS + skc * 16;
    const uint32_t bDst0 = ATB + srow * RS + skc * 16;

    auto issue = [&](int s, int it) {
        uint32_t sb = sbase + s * SSTG;
        int k0 = it * BK;
        CP_ASYNC16(sb + aDst0, aSrc0 + k0);
        CP_ASYNC16(sb + aDst1, aSrc1 + k0);
        CP_ASYNC16(sb + bDst0, bSrc0 + k0);
        CP_COMMIT();
    };

    const uint32_t aRowL = (uint32_t)(warpM * 32 + (lane & 15));
    const uint32_t aColB = (uint32_t)((lane >> 4) * 16);
    const uint32_t bRowL = (uint32_t)(warpN * 32 + (lane & 7) + ((lane >> 4) << 3));
    const uint32_t bColB = (uint32_t)(((lane >> 3) & 1) * 16);

    float acc[2][4][4] = {};

    issue(0, 0);
    issue(1, 1);

    for (int it = 0; it < nch; it++) {
        CP_WAIT(1);
        __syncthreads();
        const uint32_t stg = sbase + (it % NSTG) * SSTG;

        #pragma unroll
        for (int kk = 0; kk < BK; kk += 16) {
            uint32_t ah[2][4], bb[2][4];
            #pragma unroll
            for (int mt = 0; mt < 2; mt++) {
                uint32_t off = (aRowL + mt * 16) * RS + aColB + kk * 2;
                LDM_X4(ah[mt][0], ah[mt][1], ah[mt][2], ah[mt][3], stg + off);
            }
            #pragma unroll
            for (int nt2 = 0; nt2 < 2; nt2++) {
                uint32_t off = ATB + (bRowL + nt2 * 16) * RS + bColB + kk * 2;
                LDM_X4(bb[nt2][0], bb[nt2][1], bb[nt2][2], bb[nt2][3], stg + off);
            }
            #pragma unroll
            for (int mt = 0; mt < 2; mt++) {
                #pragma unroll
                for (int n = 0; n < 4; n++) {
                    uint32_t bf[2] = { bb[n >> 1][(n & 1) * 2], bb[n >> 1][(n & 1) * 2 + 1] };
                    MMA_F16(acc[mt][n], ah[mt], bf);
                }
            }
        }

        int nxt = it + NSTG - 1;
        if (nxt < nch) issue(nxt % NSTG, nxt);
        else           CP_COMMIT();
    }

    // ---- epilogue ----
    const int qid = lane >> 2;
    const int cid2 = (lane & 3) * 2;
    #pragma unroll
    for (int mt = 0; mt < 2; mt++) {
        #pragma unroll
        for (int hf = 0; hf < 2; hf++) {
            int row = rowBase + warpM * 32 + mt * 16 + qid + hf * 8;
            if (SCATTER) row = map_row(row);
            #pragma unroll
            for (int n = 0; n < 4; n++) {
                int col = colBase + warpN * 32 + n * 8 + cid2;
                float2 bv = *(const float2*)(bias + col);
                float ox = acc[mt][n][hf * 2 + 0] + bv.x;
                float oy = acc[mt][n][hf * 2 + 1] + bv.y;
                if (DOGELU) {
                    ox = 0.5f * ox * (1.0f + erff(ox * 0.70710678118654752f));
                    oy = 0.5f * oy * (1.0f + erff(oy * 0.70710678118654752f));
                }
                if (Ou) *(uint32_t*)(Ou + ((size_t)row * N + col) / 2) = pk_h2(ox, oy);
                else    *(float2*)(Of + (size_t)row * N + col) = make_float2(ox, oy);
            }
        }
    }
}

// ---------------------------------------------------------------------------
// Tensor-core attention (unchanged from R11/R13).
// ---------------------------------------------------------------------------
#define AT_SMEM 61440

__global__ __launch_bounds__(256, 2) void attn_mma(
    const __half* __restrict__ qkv, const float* __restrict__ rpbd,
    const float* __restrict__ mask, uint32_t* __restrict__ outp)
{
    extern __shared__ char smraw[];
    const uint32_t sbase = smem_to_u32(smraw);
    const int tid = threadIdx.x, wid = tid >> 5, lane = tid & 31;
    const int u = wid >> 1, mhalf = wid & 1;
    const int wh = blockIdx.x * 4 + u;
    const int w = wh / NH;
    const int hh = wh - w * NH;
    const size_t rowbase = (size_t)w * 64;

    const uint32_t Qs = sbase + u * 15360;
    const uint32_t Ks = Qs + 5120;
    const uint32_t Vs = Qs + 10240;

    {
        int t64 = mhalf * 32 + lane;
        int r0  = t64 >> 2;
        int seg = t64 & 3;
        const __half* base = qkv + rowbase * QKV_N + hh * 32 + seg * 8;
        #pragma unroll
        for (int it = 0; it < 4; it++) {
            int row = it * 16 + r0;
            const __half* src = base + (size_t)row * QKV_N;
            uint32_t d = row * 80 + seg * 16;
            CP_ASYNC16(Qs + d, src);
            CP_ASYNC16(Ks + d, src + 192);
            CP_ASYNC16(Vs + d, src + 384);
        }
        CP_COMMIT();
    }
    CP_WAIT(0);
    __syncthreads();

    const int qid = lane >> 2, cid = lane & 3;
    const int mbase = mhalf * 32;

    const uint32_t aRow  = (uint32_t)(mbase + (lane & 15));
    const uint32_t aColB = (uint32_t)((lane >> 4) * 16);
    const uint32_t bRow  = (uint32_t)((lane & 7) + ((lane >> 4) << 3));
    const uint32_t bColB = (uint32_t)(((lane >> 3) & 1) * 16);

    float s[2][8][4] = {};
    #pragma unroll
    for (int ks = 0; ks < 2; ks++) {
        uint32_t qf[2][4];
        #pragma unroll
        for (int mt = 0; mt < 2; mt++)
            LDM_X4(qf[mt][0], qf[mt][1], qf[mt][2], qf[mt][3],
                   Qs + (aRow + mt * 16) * 80 + aColB + ks * 32);
        #pragma unroll
        for (int p = 0; p < 4; p++) {
            uint32_t kb[4];
            LDM_X4(kb[0], kb[1], kb[2], kb[3],
                   Ks + (bRow + p * 16) * 80 + bColB + ks * 32);
            #pragma unroll
            for (int mt = 0; mt < 2; mt++) {
                #pragma unroll
                for (int nn = 0; nn < 2; nn++) {
                    uint32_t bf[2] = { kb[nn * 2], kb[nn * 2 + 1] };
                    MMA_F16(s[mt][p * 2 + nn], qf[mt], bf);
                }
            }
        }
    }

    const float* mrow = mask + (size_t)(w & 1023) * 4096;
    const float* rrow = rpbd + hh * 4096;
    uint32_t pf[2][4][4];
    float inva[2], invb[2];
    #pragma unroll
    for (int mt = 0; mt < 2; mt++) {
        int t0 = mbase + mt * 16 + qid;
        int t1 = t0 + 8;
        float mx0 = -1e30f, mx1 = -1e30f;
        #pragma unroll
        for (int n = 0; n < 8; n++) {
            int j = n * 8 + cid * 2;
            float2 r0 = *(const float2*)(rrow + t0 * 64 + j);
            float2 r1 = *(const float2*)(rrow + t1 * 64 + j);
            float2 m0 = *(const float2*)(mrow + t0 * 64 + j);
            float2 m1 = *(const float2*)(mrow + t1 * 64 + j);
            s[mt][n][0] = fmaf(s[mt][n][0], SCALE_F, r0.x + m0.x);
            s[mt][n][1] = fmaf(s[mt][n][1], SCALE_F, r0.y + m0.y);
            s[mt][n][2] = fmaf(s[mt][n][2], SCALE_F, r1.x + m1.x);
            s[mt][n][3] = fmaf(s[mt][n][3], SCALE_F, r1.y + m1.y);
            mx0 = fmaxf(mx0, fmaxf(s[mt][n][0], s[mt][n][1]));
            mx1 = fmaxf(mx1, fmaxf(s[mt][n][2], s[mt][n][3]));
        }
        mx0 = fmaxf(mx0, __shfl_xor_sync(0xffffffffu, mx0, 1));
        mx0 = fmaxf(mx0, __shfl_xor_sync(0xffffffffu, mx0, 2));
        mx1 = fmaxf(mx1, __shfl_xor_sync(0xffffffffu, mx1, 1));
        mx1 = fmaxf(mx1, __shfl_xor_sync(0xffffffffu, mx1, 2));

        float sm0 = 0.f, sm1 = 0.f;
        #pragma unroll
        for (int n = 0; n < 8; n++) {
            s[mt][n][0] = expf(s[mt][n][0] - mx0);
            s[mt][n][1] = expf(s[mt][n][1] - mx0);
            s[mt][n][2] = expf(s[mt][n][2] - mx1);
            s[mt][n][3] = expf(s[mt][n][3] - mx1);
            sm0 += s[mt][n][0] + s[mt][n][1];
            sm1 += s[mt][n][2] + s[mt][n][3];
        }
        sm0 += __shfl_xor_sync(0xffffffffu, sm0, 1);
        sm0 += __shfl_xor_sync(0xffffffffu, sm0, 2);
        sm1 += __shfl_xor_sync(0xffffffffu, sm1, 1);
        sm1 += __shfl_xor_sync(0xffffffffu, sm1, 2);
        inva[mt] = 1.f / sm0;
        invb[mt] = 1.f / sm1;

        #pragma unroll
        for (int k2 = 0; k2 < 4; k2++) {
            pf[mt][k2][0] = pk_h2(s[mt][2 * k2][0],     s[mt][2 * k2][1]);
            pf[mt][k2][1] = pk_h2(s[mt][2 * k2][2],     s[mt][2 * k2][3]);
            pf[mt][k2][2] = pk_h2(s[mt][2 * k2 + 1][0], s[mt][2 * k2 + 1][1]);
            pf[mt][k2][3] = pk_h2(s[mt][2 * k2 + 1][2], s[mt][2 * k2 + 1][3]);
        }
    }

    float o[2][4][4] = {};
    const uint32_t vRow  = (uint32_t)(lane & 15);
    const uint32_t vColB = (uint32_t)((lane >> 4) * 16);
    #pragma unroll
    for (int k2 = 0; k2 < 4; k2++) {
        #pragma unroll
        for (int p = 0; p < 2; p++) {
            uint32_t vb[4];
            LDM_X4_T(vb[0], vb[1], vb[2], vb[3],
                     Vs + (k2 * 16 + vRow) * 80 + vColB + p * 32);
            #pragma unroll
            for (int mt = 0; mt < 2; mt++) {
                #pragma unroll
                for (int nn = 0; nn < 2; nn++) {
                    uint32_t bf[2] = { vb[nn * 2], vb[nn * 2 + 1] };
                    MMA_F16(o[mt][p * 2 + nn], pf[mt][k2], bf);
                }
            }
        }
    }

    #pragma unroll
    for (int mt = 0; mt < 2; mt++) {
        int t0 = mbase + mt * 16 + qid;
        int t1 = t0 + 8;
        uint32_t* o0 = outp + ((rowbase + t0) * C_DIM + hh * 32) / 2;
        uint32_t* o1 = outp + ((rowbase + t1) * C_DIM + hh * 32) / 2;
        #pragma unroll
        for (int nt = 0; nt < 4; nt++) {
            int c2 = (nt * 8 + cid * 2) >> 1;
            o0[c2] = pk_h2(o[mt][nt][0] * inva[mt], o[mt][nt][1] * inva[mt]);
            o1[c2] = pk_h2(o[mt][nt][2] * invb[mt], o[mt][nt][3] * invb[mt]);
        }
    }
}

// ---------------------------------------------------------------------------
// LN kernels (unchanged)
// ---------------------------------------------------------------------------
__global__ __launch_bounds__(256) void ln1_k(
    const float* __restrict__ y, const float* __restrict__ resx,
    const float* __restrict__ g, const float* __restrict__ b,
    float* __restrict__ of, uint32_t* __restrict__ oh)
{
    const size_t token = (size_t)blockIdx.x * 8 + (threadIdx.x >> 5);
    const int lane = threadIdx.x & 31;
    const size_t yb = token * C_DIM;

    float v[6];
    float sum = 0.f;
    #pragma unroll
    for (int i = 0; i < 6; i++) { v[i] = y[yb + lane + 32 * i]; sum += v[i]; }
    #pragma unroll
    for (int o = 16; o; o >>= 1) sum += __shfl_xor_sync(0xffffffffu, sum, o);
    const float mu = sum * (1.f / 192.f);
    float sq = 0.f;
    #pragma unroll
    for (int i = 0; i < 6; i++) { float d = v[i] - mu; sq = fmaf(d, d, sq); }
    #pragma unroll
    for (int o = 16; o; o >>= 1) sq += __shfl_xor_sync(0xffffffffu, sq, o);
    const float inv = rsqrtf(sq * (1.f / 192.f) + 1e-5f);

    #pragma unroll
    for (int i = 0; i < 6; i++) {
        int c = lane + 32 * i;
        float r = resx[yb + c] + (v[i] - mu) * inv * g[c] + b[c];
        of[yb + c] = r;
        ((__half*)oh)[yb + c] = __float2half_rn(r);
    }
}

__global__ __launch_bounds__(256) void ln2_k(
    const float* __restrict__ y, const float* __restrict__ r,
    const float* __restrict__ g, const float* __restrict__ b,
    float* __restrict__ outp)
{
    const size_t token = (size_t)blockIdx.x * 8 + (threadIdx.x >> 5);
    const int lane = threadIdx.x & 31;
    const size_t yb = token * C_DIM;

    float v[6];
    float sum = 0.f;
    #pragma unroll
    for (int i = 0; i < 6; i++) { v[i] = y[yb + lane + 32 * i]; sum += v[i]; }
    #pragma unroll
    for (int o = 16; o; o >>= 1) sum += __shfl_xor_sync(0xffffffffu, sum, o);
    const float mu = sum * (1.f / 192.f);
    float sq = 0.f;
    #pragma unroll
    for (int i = 0; i < 6; i++) { float d = v[i] - mu; sq = fmaf(d, d, sq); }
    #pragma unroll
    for (int o = 16; o; o >>= 1) sq += __shfl_xor_sync(0xffffffffu, sq, o);
    const float inv = rsqrtf(sq * (1.f / 192.f) + 1e-5f);

    #pragma unroll
    for (int i = 0; i < 6; i++) {
        int c = lane + 32 * i;
        outp[yb + c] = r[yb + c] + (v[i] - mu) * inv * g[c] + b[c];
    }
}

// ---------------------------------------------------------------------------
// Launch (qkv GEMM at capture slot 4)
// ---------------------------------------------------------------------------
extern "C" void kernel_launch(void* const* d_in, const int* in_sizes, int n_in,
                              void* d_out, int out_size)
{
    const float* x      = (const float*)d_in[0];
    const float* mask   = (const float*)d_in[1];
    const int*   relidx = (const int*)  d_in[2];
    const float* qkv_w  = (const float*)d_in[3];
    const float* qkv_b  = (const float*)d_in[4];
    const float* proj_w = (const float*)d_in[5];
    const float* proj_b = (const float*)d_in[6];
    const float* rpb    = (const float*)d_in[7];
    const float* n1g    = (const float*)d_in[8];
    const float* n1b    = (const float*)d_in[9];
    const float* n2g    = (const float*)d_in[10];
    const float* n2b    = (const float*)d_in[11];
    const float* fc1w   = (const float*)d_in[12];
    const float* fc1b   = (const float*)d_in[13];
    const float* fc2w   = (const float*)d_in[14];
    const float* fc2b   = (const float*)d_in[15];
    float* out = (float*)d_out;

    char* pool;
    cudaGetSymbolAddress((void**)&pool, g_pool);
    __half*   q   = (__half*)(pool);
    __half*   h   = (__half*)(pool);
    __half*   xb  = (__half*)(pool + OFF_XA);
    __half*   a   = (__half*)(pool + OFF_XA);
    float*    tb  = (float*)(pool + OFF_T);
    float*    x1f = (float*)(pool + OFF_X1F);
    uint32_t* x1h = (uint32_t*)(pool + OFF_X1H);

    __half *wq, *wp, *w1, *w2;
    float* rpbd;
    cudaGetSymbolAddress((void**)&wq, g_wq);
    cudaGetSymbolAddress((void**)&wp, g_wp);
    cudaGetSymbolAddress((void**)&w1, g_w1);
    cudaGetSymbolAddress((void**)&w2, g_w2);
    cudaGetSymbolAddress((void**)&rpbd, g_rpbd);

    cudaFuncSetAttribute(mm_p3<false, false>, cudaFuncAttributeMaxDynamicSharedMemorySize, MMSMEM);
    cudaFuncSetAttribute(mm_p3<true,  false>, cudaFuncAttributeMaxDynamicSharedMemorySize, MMSMEM);
    cudaFuncSetAttribute(mm_p3<false, true >, cudaFuncAttributeMaxDynamicSharedMemorySize, MMSMEM);
    cudaFuncSetAttribute(attn_mma, cudaFuncAttributeMaxDynamicSharedMemorySize, AT_SMEM);

    // 1. x -> window-ordered fp16
    prep_x<<<(M_TOT * 48) / 256, 256>>>(x, (uint32_t*)xb);
    // 2. dense rpb
    prep_rpb<<<(NH * 4096) / 256, 256>>>(rpb, relidx, rpbd);
    // 3. qkv weights
    prep_w<<<(QKV_N * (C_DIM / 4)) / 256, 256>>>(qkv_w, (uint32_t*)wq, C_DIM);
    // 4. qkv GEMM  (capture slot)
    mm_p3<false, false><<<dim3(QKV_N / 64, M_TOT / 128), 256, MMSMEM>>>(
        xb, wq, qkv_b, (uint32_t*)q, nullptr, QKV_N, C_DIM);
    // 5. attention (tensor cores)
    attn_mma<<<NWIN * NH / 4, 256, AT_SMEM>>>(q, rpbd, mask, (uint32_t*)a);
    // 6. proj weights
    prep_w<<<(C_DIM * (C_DIM / 4)) / 256, 256>>>(proj_w, (uint32_t*)wp, C_DIM);
    // 7. proj GEMM + scatter, fp32 out
    mm_p3<true, false><<<dim3(C_DIM / 64, M_TOT / 128), 256, MMSMEM>>>(
        a, wp, proj_b, nullptr, tb, C_DIM, C_DIM);
    // 8. LN1
    ln1_k<<<M_TOT / 8, 256>>>(tb, x, n1g, n1b, x1f, x1h);
    // 9. fc1 weights
    prep_w<<<(HIDDEN * (C_DIM / 4)) / 256, 256>>>(fc1w, (uint32_t*)w1, C_DIM);
    // 10. fc1 + GELU
    mm_p3<false, true><<<dim3(HIDDEN / 64, M_TOT / 128), 256, MMSMEM>>>(
        (const __half*)x1h, w1, fc1b, (uint32_t*)h, nullptr, HIDDEN, C_DIM);
    // 11. fc2 weights
    prep_w<<<(C_DIM * (HIDDEN / 4)) / 256, 256>>>(fc2w, (uint32_t*)w2, HIDDEN);
    // 12. fc2
    mm_p3<false, false><<<dim3(C_DIM / 64, M_TOT / 128), 256, MMSMEM>>>(
        h, w2, fc2b, nullptr, tb, C_DIM, HIDDEN);
    // 13. LN2 -> out
    ln2_k<<<M_TOT / 8, 256>>>(tb, x1f, n2g, n2b, out);
}

// round 16
// speedup vs baseline: 1.1447x; 1.1447x over previous
#include <cuda_runtime.h>
#include <cuda_fp16.h>
#include <math.h>
#include <stdint.h>

// ---------------------------------------------------------------------------
#define C_DIM   192
#define NH      6
#define NWIN    4096
#define M_TOT   262144
#define HIDDEN  768
#define QKV_N   576
#define SCALE_F 0.17677669529663687f

// ---------------------------------------------------------------------------
#define SZ_H16  ((size_t)M_TOT * HIDDEN * 2)
#define SZ_CD16 ((size_t)M_TOT * C_DIM * 2)
#define SZ_CD32 ((size_t)M_TOT * C_DIM * 4)
#define OFF_XA  (SZ_H16)
#define OFF_T   (OFF_XA + SZ_CD16)
#define OFF_X1F (OFF_T + SZ_CD32)
#define OFF_X1H (OFF_X1F + SZ_CD32)
#define POOLSZ  (OFF_X1H + SZ_CD16)

__device__ __align__(256) char g_pool[POOLSZ];

__device__ __half g_wq[QKV_N * C_DIM];
__device__ __half g_wp[C_DIM * C_DIM];
__device__ __half g_w1[HIDDEN * C_DIM];
__device__ __half g_w2[C_DIM * HIDDEN];
__device__ float  g_rpbd[NH * 64 * 64];

// ---------------------------------------------------------------------------
__device__ __forceinline__ int map_row(int m) {
    int w    = m >> 6;
    int t    = m & 63;
    int b    = w >> 10;
    int widx = w & 1023;
    int wh   = widx >> 5;
    int ww   = widx & 31;
    int r    = t >> 3;
    int c    = t & 7;
    int h    = (wh * 8 + r + 4) & 255;
    int wc   = (ww * 8 + c + 4) & 255;
    return (b << 16) | (h << 8) | wc;
}

__device__ __forceinline__ uint32_t smem_to_u32(const void* p) {
    uint32_t a;
    asm("{ .reg .u64 t; cvta.to.shared.u64 t, %1; cvt.u32.u64 %0, t; }" : "=r"(a) : "l"(p));
    return a;
}

#define CP_ASYNC16(dst, src) \
    asm volatile("cp.async.cg.shared.global [%0], [%1], 16;" :: "r"(dst), "l"(src))
#define CP_COMMIT() asm volatile("cp.async.commit_group;")
#define CP_WAIT(n)  asm volatile("cp.async.wait_group %0;" :: "n"(n))

#define LDM_X4(r0, r1, r2, r3, addr) \
    asm volatile("ldmatrix.sync.aligned.m8n8.x4.shared.b16 {%0,%1,%2,%3}, [%4];" \
                 : "=r"(r0), "=r"(r1), "=r"(r2), "=r"(r3) : "r"(addr))
#define LDM_X4_T(r0, r1, r2, r3, addr) \
    asm volatile("ldmatrix.sync.aligned.m8n8.x4.trans.shared.b16 {%0,%1,%2,%3}, [%4];" \
                 : "=r"(r0), "=r"(r1), "=r"(r2), "=r"(r3) : "r"(addr))

#define MMA_F16(d, a, b) \
    asm volatile("mma.sync.aligned.m16n8k16.row.col.f32.f16.f16.f32 " \
                 "{%0,%1,%2,%3}, {%4,%5,%6,%7}, {%8,%9}, {%0,%1,%2,%3};" \
                 : "+f"((d)[0]), "+f"((d)[1]), "+f"((d)[2]), "+f"((d)[3]) \
                 : "r"((a)[0]), "r"((a)[1]), "r"((a)[2]), "r"((a)[3]), \
                   "r"((b)[0]), "r"((b)[1]))

__device__ __forceinline__ uint32_t pk_h2(float x, float y) {
    __half2 t = __floats2half2_rn(x, y);
    return *(uint32_t*)&t;
}

// ---------------------------------------------------------------------------
// Prep kernels
// ---------------------------------------------------------------------------
__global__ __launch_bounds__(256) void prep_x(
    const float* __restrict__ x, uint32_t* __restrict__ xo)
{
    int idx = blockIdx.x * 256 + threadIdx.x;
    int m = idx / 48, c4 = idx % 48;
    float4 v = *(const float4*)(x + (size_t)map_row(m) * C_DIM + c4 * 4);
    *(uint2*)(xo + ((size_t)m * C_DIM + c4 * 4) / 2) =
        make_uint2(pk_h2(v.x, v.y), pk_h2(v.z, v.w));
}

__device__ __forceinline__ void cvt_w(const float* w, uint32_t* wo, int item, int K) {
    int k4 = K / 4;
    int row = item / k4, c4 = item % k4;
    float4 v = *(const float4*)(w + (size_t)row * K + c4 * 4);
    *(uint2*)(wo + ((size_t)row * K + c4 * 4) / 2) =
        make_uint2(pk_h2(v.x, v.y), pk_h2(v.z, v.w));
}

// Fused prep: all 4 weight conversions + dense rpb in one launch.
// Segments (item index): [0,27648) wq | [27648,36864) wp | [36864,73728) w1
//                        | [73728,110592) w2 | [110592,135168) rpb
__global__ __launch_bounds__(256) void prep_all(
    const float* __restrict__ qkv_w, const float* __restrict__ proj_w,
    const float* __restrict__ fc1w,  const float* __restrict__ fc2w,
    const float* __restrict__ rpb_table, const int* __restrict__ rel_idx,
    uint32_t* __restrict__ wq, uint32_t* __restrict__ wp,
    uint32_t* __restrict__ w1, uint32_t* __restrict__ w2,
    float* __restrict__ rpbd)
{
    int idx = blockIdx.x * 256 + threadIdx.x;
    if (idx < 27648)       cvt_w(qkv_w,  wq, idx,           C_DIM);
    else if (idx < 36864)  cvt_w(proj_w, wp, idx - 27648,   C_DIM);
    else if (idx < 73728)  cvt_w(fc1w,   w1, idx - 36864,   C_DIM);
    else if (idx < 110592) cvt_w(fc2w,   w2, idx - 73728,   HIDDEN);
    else {
        int i = idx - 110592;                       // NH*4096 items
        int h = i >> 12, tj = i & 4095;
        rpbd[i] = rpb_table[rel_idx[tj] * NH + h];
    }
}

// ---------------------------------------------------------------------------
// Pipelined fp16 HMMA GEMM (R13 config — best measured).
// BM=256, BN=64, BK=64, 256 thr, warps 4(M) x 2(N), warp tile 64x32,
// 2-stage cp.async.
// ---------------------------------------------------------------------------
#define BM   256
#define BK   64
#define RS   144
#define ATB  (256 * RS)
#define BTB  (64 * RS)
#define SSTG (ATB + BTB)
#define MMSMEM (2 * SSTG)

template<bool SCATTER, bool DOGELU>
__global__ __launch_bounds__(256, 2) void mm_f16(
    const __half* __restrict__ A, const __half* __restrict__ W,
    const float* __restrict__ bias, uint32_t* __restrict__ Ou,
    float* __restrict__ Of, int N, int K)
{
    extern __shared__ char sm[];
    const uint32_t sbase = smem_to_u32(sm);

    const int tid = threadIdx.x, wid = tid >> 5, lane = tid & 31;
    const int warpM = wid & 3, warpN = wid >> 2;
    const int rowBase = blockIdx.y * BM;
    const int colBase = blockIdx.x * 64;
    const int nch = K / BK;

    const __half* aSrc0 = A + (size_t)(rowBase + (tid >> 3)) * K + (tid & 7) * 8;
    const __half* bSrc0 = W + (size_t)(colBase + (tid >> 3)) * K + (tid & 7) * 8;
    const uint32_t dDst0 = (tid >> 3) * RS + (tid & 7) * 16;
    const size_t aStep = (size_t)32 * K;

    auto issue = [&](int s, int it) {
        uint32_t sb = sbase + s * SSTG;
        int k0 = it * BK;
        #pragma unroll
        for (int t = 0; t < 8; t++)
            CP_ASYNC16(sb + dDst0 + t * (32 * RS), aSrc0 + k0 + t * aStep);
        #pragma unroll
        for (int t = 0; t < 2; t++)
            CP_ASYNC16(sb + ATB + dDst0 + t * (32 * RS), bSrc0 + k0 + t * aStep);
        CP_COMMIT();
    };

    const uint32_t aRowL = (uint32_t)(warpM * 64 + (lane & 15));
    const uint32_t aColB = (uint32_t)((lane >> 4) * 16);
    const uint32_t bRowL = (uint32_t)(warpN * 32 + (lane & 7) + ((lane >> 4) << 3));
    const uint32_t bColB = (uint32_t)(((lane >> 3) & 1) * 16);

    float acc[4][4][4] = {};

    issue(0, 0);

    for (int it = 0; it < nch; it++) {
        CP_WAIT(0);
        __syncthreads();
        if (it + 1 < nch) issue((it + 1) & 1, it + 1);

        const uint32_t stg = sbase + (it & 1) * SSTG;
        #pragma unroll
        for (int kk = 0; kk < BK; kk += 16) {
            uint32_t ah[4][4], bb[2][4];
            #pragma unroll
            for (int mt = 0; mt < 4; mt++) {
                uint32_t off = (aRowL + mt * 16) * RS + aColB + kk * 2;
                LDM_X4(ah[mt][0], ah[mt][1], ah[mt][2], ah[mt][3], stg + off);
            }
            #pragma unroll
            for (int nt2 = 0; nt2 < 2; nt2++) {
                uint32_t off = ATB + (bRowL + nt2 * 16) * RS + bColB + kk * 2;
                LDM_X4(bb[nt2][0], bb[nt2][1], bb[nt2][2], bb[nt2][3], stg + off);
            }
            #pragma unroll
            for (int mt = 0; mt < 4; mt++) {
                #pragma unroll
                for (int n = 0; n < 4; n++) {
                    uint32_t bf[2] = { bb[n >> 1][(n & 1) * 2], bb[n >> 1][(n & 1) * 2 + 1] };
                    MMA_F16(acc[mt][n], ah[mt], bf);
                }
            }
        }
    }

    const int qid = lane >> 2;
    const int cid2 = (lane & 3) * 2;
    #pragma unroll
    for (int mt = 0; mt < 4; mt++) {
        #pragma unroll
        for (int hf = 0; hf < 2; hf++) {
            int row = rowBase + warpM * 64 + mt * 16 + qid + hf * 8;
            if (SCATTER) row = map_row(row);
            #pragma unroll
            for (int n = 0; n < 4; n++) {
                int col = colBase + warpN * 32 + n * 8 + cid2;
                float2 bv = *(const float2*)(bias + col);
                float ox = acc[mt][n][hf * 2 + 0] + bv.x;
                float oy = acc[mt][n][hf * 2 + 1] + bv.y;
                if (DOGELU) {
                    ox = 0.5f * ox * (1.0f + erff(ox * 0.70710678118654752f));
                    oy = 0.5f * oy * (1.0f + erff(oy * 0.70710678118654752f));
                }
                if (Ou) *(uint32_t*)(Ou + ((size_t)row * N + col) / 2) = pk_h2(ox, oy);
                else    *(float2*)(Of + (size_t)row * N + col) = make_float2(ox, oy);
            }
        }
    }
}

// ---------------------------------------------------------------------------
// Tensor-core attention (unchanged).
// ---------------------------------------------------------------------------
#define AT_SMEM 61440

__global__ __launch_bounds__(256, 2) void attn_mma(
    const __half* __restrict__ qkv, const float* __restrict__ rpbd,
    const float* __restrict__ mask, uint32_t* __restrict__ outp)
{
    extern __shared__ char smraw[];
    const uint32_t sbase = smem_to_u32(smraw);
    const int tid = threadIdx.x, wid = tid >> 5, lane = tid & 31;
    const int u = wid >> 1, mhalf = wid & 1;
    const int wh = blockIdx.x * 4 + u;
    const int w = wh / NH;
    const int hh = wh - w * NH;
    const size_t rowbase = (size_t)w * 64;

    const uint32_t Qs = sbase + u * 15360;
    const uint32_t Ks = Qs + 5120;
    const uint32_t Vs = Qs + 10240;

    {
        int t64 = mhalf * 32 + lane;
        int r0  = t64 >> 2;
        int seg = t64 & 3;
        const __half* base = qkv + rowbase * QKV_N + hh * 32 + seg * 8;
        #pragma unroll
        for (int it = 0; it < 4; it++) {
            int row = it * 16 + r0;
            const __half* src = base + (size_t)row * QKV_N;
            uint32_t d = row * 80 + seg * 16;
            CP_ASYNC16(Qs + d, src);
            CP_ASYNC16(Ks + d, src + 192);
            CP_ASYNC16(Vs + d, src + 384);
        }
        CP_COMMIT();
    }
    CP_WAIT(0);
    __syncthreads();

    const int qid = lane >> 2, cid = lane & 3;
    const int mbase = mhalf * 32;

    const uint32_t aRow  = (uint32_t)(mbase + (lane & 15));
    const uint32_t aColB = (uint32_t)((lane >> 4) * 16);
    const uint32_t bRow  = (uint32_t)((lane & 7) + ((lane >> 4) << 3));
    const uint32_t bColB = (uint32_t)(((lane >> 3) & 1) * 16);

    float s[2][8][4] = {};
    #pragma unroll
    for (int ks = 0; ks < 2; ks++) {
        uint32_t qf[2][4];
        #pragma unroll
        for (int mt = 0; mt < 2; mt++)
            LDM_X4(qf[mt][0], qf[mt][1], qf[mt][2], qf[mt][3],
                   Qs + (aRow + mt * 16) * 80 + aColB + ks * 32);
        #pragma unroll
        for (int p = 0; p < 4; p++) {
            uint32_t kb[4];
            LDM_X4(kb[0], kb[1], kb[2], kb[3],
                   Ks + (bRow + p * 16) * 80 + bColB + ks * 32);
            #pragma unroll
            for (int mt = 0; mt < 2; mt++) {
                #pragma unroll
                for (int nn = 0; nn < 2; nn++) {
                    uint32_t bf[2] = { kb[nn * 2], kb[nn * 2 + 1] };
                    MMA_F16(s[mt][p * 2 + nn], qf[mt], bf);
                }
            }
        }
    }

    const float* mrow = mask + (size_t)(w & 1023) * 4096;
    const float* rrow = rpbd + hh * 4096;
    uint32_t pf[2][4][4];
    float inva[2], invb[2];
    #pragma unroll
    for (int mt = 0; mt < 2; mt++) {
        int t0 = mbase + mt * 16 + qid;
        int t1 = t0 + 8;
        float mx0 = -1e30f, mx1 = -1e30f;
        #pragma unroll
        for (int n = 0; n < 8; n++) {
            int j = n * 8 + cid * 2;
            float2 r0 = *(const float2*)(rrow + t0 * 64 + j);
            float2 r1 = *(const float2*)(rrow + t1 * 64 + j);
            float2 m0 = *(const float2*)(mrow + t0 * 64 + j);
            float2 m1 = *(const float2*)(mrow + t1 * 64 + j);
            s[mt][n][0] = fmaf(s[mt][n][0], SCALE_F, r0.x + m0.x);
            s[mt][n][1] = fmaf(s[mt][n][1], SCALE_F, r0.y + m0.y);
            s[mt][n][2] = fmaf(s[mt][n][2], SCALE_F, r1.x + m1.x);
            s[mt][n][3] = fmaf(s[mt][n][3], SCALE_F, r1.y + m1.y);
            mx0 = fmaxf(mx0, fmaxf(s[mt][n][0], s[mt][n][1]));
            mx1 = fmaxf(mx1, fmaxf(s[mt][n][2], s[mt][n][3]));
        }
        mx0 = fmaxf(mx0, __shfl_xor_sync(0xffffffffu, mx0, 1));
        mx0 = fmaxf(mx0, __shfl_xor_sync(0xffffffffu, mx0, 2));
        mx1 = fmaxf(mx1, __shfl_xor_sync(0xffffffffu, mx1, 1));
        mx1 = fmaxf(mx1, __shfl_xor_sync(0xffffffffu, mx1, 2));

        float sm0 = 0.f, sm1 = 0.f;
        #pragma unroll
        for (int n = 0; n < 8; n++) {
            s[mt][n][0] = expf(s[mt][n][0] - mx0);
            s[mt][n][1] = expf(s[mt][n][1] - mx0);
            s[mt][n][2] = expf(s[mt][n][2] - mx1);
            s[mt][n][3] = expf(s[mt][n][3] - mx1);
            sm0 += s[mt][n][0] + s[mt][n][1];
            sm1 += s[mt][n][2] + s[mt][n][3];
        }
        sm0 += __shfl_xor_sync(0xffffffffu, sm0, 1);
        sm0 += __shfl_xor_sync(0xffffffffu, sm0, 2);
        sm1 += __shfl_xor_sync(0xffffffffu, sm1, 1);
        sm1 += __shfl_xor_sync(0xffffffffu, sm1, 2);
        inva[mt] = 1.f / sm0;
        invb[mt] = 1.f / sm1;

        #pragma unroll
        for (int k2 = 0; k2 < 4; k2++) {
            pf[mt][k2][0] = pk_h2(s[mt][2 * k2][0],     s[mt][2 * k2][1]);
            pf[mt][k2][1] = pk_h2(s[mt][2 * k2][2],     s[mt][2 * k2][3]);
            pf[mt][k2][2] = pk_h2(s[mt][2 * k2 + 1][0], s[mt][2 * k2 + 1][1]);
            pf[mt][k2][3] = pk_h2(s[mt][2 * k2 + 1][2], s[mt][2 * k2 + 1][3]);
        }
    }

    float o[2][4][4] = {};
    const uint32_t vRow  = (uint32_t)(lane & 15);
    const uint32_t vColB = (uint32_t)((lane >> 4) * 16);
    #pragma unroll
    for (int k2 = 0; k2 < 4; k2++) {
        #pragma unroll
        for (int p = 0; p < 2; p++) {
            uint32_t vb[4];
            LDM_X4_T(vb[0], vb[1], vb[2], vb[3],
                     Vs + (k2 * 16 + vRow) * 80 + vColB + p * 32);
            #pragma unroll
            for (int mt = 0; mt < 2; mt++) {
                #pragma unroll
                for (int nn = 0; nn < 2; nn++) {
                    uint32_t bf[2] = { vb[nn * 2], vb[nn * 2 + 1] };
                    MMA_F16(o[mt][p * 2 + nn], pf[mt][k2], bf);
                }
            }
        }
    }

    #pragma unroll
    for (int mt = 0; mt < 2; mt++) {
        int t0 = mbase + mt * 16 + qid;
        int t1 = t0 + 8;
        uint32_t* o0 = outp + ((rowbase + t0) * C_DIM + hh * 32) / 2;
        uint32_t* o1 = outp + ((rowbase + t1) * C_DIM + hh * 32) / 2;
        #pragma unroll
        for (int nt = 0; nt < 4; nt++) {
            int c2 = (nt * 8 + cid * 2) >> 1;
            o0[c2] = pk_h2(o[mt][nt][0] * inva[mt], o[mt][nt][1] * inva[mt]);
            o1[c2] = pk_h2(o[mt][nt][2] * invb[mt], o[mt][nt][3] * invb[mt]);
        }
    }
}

// ---------------------------------------------------------------------------
// LN kernels (unchanged)
// ---------------------------------------------------------------------------
__global__ __launch_bounds__(256) void ln1_k(
    const float* __restrict__ y, const float* __restrict__ resx,
    const float* __restrict__ g, const float* __restrict__ b,
    float* __restrict__ of, uint32_t* __restrict__ oh)
{
    const size_t token = (size_t)blockIdx.x * 8 + (threadIdx.x >> 5);
    const int lane = threadIdx.x & 31;
    const size_t yb = token * C_DIM;

    float v[6];
    float sum = 0.f;
    #pragma unroll
    for (int i = 0; i < 6; i++) { v[i] = y[yb + lane + 32 * i]; sum += v[i]; }
    #pragma unroll
    for (int o = 16; o; o >>= 1) sum += __shfl_xor_sync(0xffffffffu, sum, o);
    const float mu = sum * (1.f / 192.f);
    float sq = 0.f;
    #pragma unroll
    for (int i = 0; i < 6; i++) { float d = v[i] - mu; sq = fmaf(d, d, sq); }
    #pragma unroll
    for (int o = 16; o; o >>= 1) sq += __shfl_xor_sync(0xffffffffu, sq, o);
    const float inv = rsqrtf(sq * (1.f / 192.f) + 1e-5f);

    #pragma unroll
    for (int i = 0; i < 6; i++) {
        int c = lane + 32 * i;
        float r = resx[yb + c] + (v[i] - mu) * inv * g[c] + b[c];
        of[yb + c] = r;
        ((__half*)oh)[yb + c] = __float2half_rn(r);
    }
}

__global__ __launch_bounds__(256) void ln2_k(
    const float* __restrict__ y, const float* __restrict__ r,
    const float* __restrict__ g, const float* __restrict__ b,
    float* __restrict__ outp)
{
    const size_t token = (size_t)blockIdx.x * 8 + (threadIdx.x >> 5);
    const int lane = threadIdx.x & 31;
    const size_t yb = token * C_DIM;

    float v[6];
    float sum = 0.f;
    #pragma unroll
    for (int i = 0; i < 6; i++) { v[i] = y[yb + lane + 32 * i]; sum += v[i]; }
    #pragma unroll
    for (int o = 16; o; o >>= 1) sum += __shfl_xor_sync(0xffffffffu, sum, o);
    const float mu = sum * (1.f / 192.f);
    float sq = 0.f;
    #pragma unroll
    for (int i = 0; i < 6; i++) { float d = v[i] - mu; sq = fmaf(d, d, sq); }
    #pragma unroll
    for (int o = 16; o; o >>= 1) sq += __shfl_xor_sync(0xffffffffu, sq, o);
    const float inv = rsqrtf(sq * (1.f / 192.f) + 1e-5f);

    #pragma unroll
    for (int i = 0; i < 6; i++) {
        int c = lane + 32 * i;
        outp[yb + c] = r[yb + c] + (v[i] - mu) * inv * g[c] + b[c];
    }
}

// ---------------------------------------------------------------------------
// Launch (attn_mma at capture slot 4)
// ---------------------------------------------------------------------------
extern "C" void kernel_launch(void* const* d_in, const int* in_sizes, int n_in,
                              void* d_out, int out_size)
{
    const float* x      = (const float*)d_in[0];
    const float* mask   = (const float*)d_in[1];
    const int*   relidx = (const int*)  d_in[2];
    const float* qkv_w  = (const float*)d_in[3];
    const float* qkv_b  = (const float*)d_in[4];
    const float* proj_w = (const float*)d_in[5];
    const float* proj_b = (const float*)d_in[6];
    const float* rpb    = (const float*)d_in[7];
    const float* n1g    = (const float*)d_in[8];
    const float* n1b    = (const float*)d_in[9];
    const float* n2g    = (const float*)d_in[10];
    const float* n2b    = (const float*)d_in[11];
    const float* fc1w   = (const float*)d_in[12];
    const float* fc1b   = (const float*)d_in[13];
    const float* fc2w   = (const float*)d_in[14];
    const float* fc2b   = (const float*)d_in[15];
    float* out = (float*)d_out;

    char* pool;
    cudaGetSymbolAddress((void**)&pool, g_pool);
    __half*   q   = (__half*)(pool);
    __half*   h   = (__half*)(pool);
    __half*   xb  = (__half*)(pool + OFF_XA);
    __half*   a   = (__half*)(pool + OFF_XA);
    float*    tb  = (float*)(pool + OFF_T);
    float*    x1f = (float*)(pool + OFF_X1F);
    uint32_t* x1h = (uint32_t*)(pool + OFF_X1H);

    __half *wq, *wp, *w1, *w2;
    float* rpbd;
    cudaGetSymbolAddress((void**)&wq, g_wq);
    cudaGetSymbolAddress((void**)&wp, g_wp);
    cudaGetSymbolAddress((void**)&w1, g_w1);
    cudaGetSymbolAddress((void**)&w2, g_w2);
    cudaGetSymbolAddress((void**)&rpbd, g_rpbd);

    cudaFuncSetAttribute(mm_f16<false, false>, cudaFuncAttributeMaxDynamicSharedMemorySize, MMSMEM);
    cudaFuncSetAttribute(mm_f16<true,  false>, cudaFuncAttributeMaxDynamicSharedMemorySize, MMSMEM);
    cudaFuncSetAttribute(mm_f16<false, true >, cudaFuncAttributeMaxDynamicSharedMemorySize, MMSMEM);
    cudaFuncSetAttribute(attn_mma, cudaFuncAttributeMaxDynamicSharedMemorySize, AT_SMEM);

    // 1. x -> window-ordered fp16
    prep_x<<<(M_TOT * 48) / 256, 256>>>(x, (uint32_t*)xb);
    // 2. all weight preps + dense rpb (fused; 135168 items)
    prep_all<<<135168 / 256, 256>>>(qkv_w, proj_w, fc1w, fc2w, rpb, relidx,
                                    (uint32_t*)wq, (uint32_t*)wp,
                                    (uint32_t*)w1, (uint32_t*)w2, rpbd);
    // 3. qkv GEMM
    mm_f16<false, false><<<dim3(QKV_N / 64, M_TOT / BM), 256, MMSMEM>>>(
        xb, wq, qkv_b, (uint32_t*)q, nullptr, QKV_N, C_DIM);
    // 4. attention (capture slot)
    attn_mma<<<NWIN * NH / 4, 256, AT_SMEM>>>(q, rpbd, mask, (uint32_t*)a);
    // 5. proj GEMM + scatter, fp32 out
    mm_f16<true, false><<<dim3(C_DIM / 64, M_TOT / BM), 256, MMSMEM>>>(
        a, wp, proj_b, nullptr, tb, C_DIM, C_DIM);
    // 6. LN1
    ln1_k<<<M_TOT / 8, 256>>>(tb, x, n1g, n1b, x1f, x1h);
    // 7. fc1 + GELU
    mm_f16<false, true><<<dim3(HIDDEN / 64, M_TOT / BM), 256, MMSMEM>>>(
        (const __half*)x1h, w1, fc1b, (uint32_t*)h, nullptr, HIDDEN, C_DIM);
    // 8. fc2
    mm_f16<false, false><<<dim3(C_DIM / 64, M_TOT / BM), 256, MMSMEM>>>(
        h, w2, fc2b, nullptr, tb, C_DIM, HIDDEN);
    // 9. LN2 -> out
    ln2_k<<<M_TOT / 8, 256>>>(tb, x1f, n2g, n2b, out);
}

// round 17
// speedup vs baseline: 1.1665x; 1.0190x over previous
#include <cuda_runtime.h>
#include <cuda_fp16.h>
#include <math.h>
#include <stdint.h>

// ---------------------------------------------------------------------------
#define C_DIM   192
#define NH      6
#define NWIN    4096
#define M_TOT   262144
#define HIDDEN  768
#define QKV_N   576
#define SCALE_F 0.17677669529663687f
#define L2E_F   1.4426950408889634f

// ---------------------------------------------------------------------------
#define SZ_H16  ((size_t)M_TOT * HIDDEN * 2)
#define SZ_CD16 ((size_t)M_TOT * C_DIM * 2)
#define SZ_CD32 ((size_t)M_TOT * C_DIM * 4)
#define OFF_XA  (SZ_H16)
#define OFF_T   (OFF_XA + SZ_CD16)
#define OFF_X1F (OFF_T + SZ_CD32)
#define OFF_X1H (OFF_X1F + SZ_CD32)
#define POOLSZ  (OFF_X1H + SZ_CD16)

__device__ __align__(256) char g_pool[POOLSZ];

__device__ __half g_wq[QKV_N * C_DIM];
__device__ __half g_wp[C_DIM * C_DIM];
__device__ __half g_w1[HIDDEN * C_DIM];
__device__ __half g_w2[C_DIM * HIDDEN];
__device__ __half g_biasc[(size_t)1024 * NH * 64 * 64];   // combined rpb+mask, fp16

// ---------------------------------------------------------------------------
__device__ __forceinline__ int map_row(int m) {
    int w    = m >> 6;
    int t    = m & 63;
    int b    = w >> 10;
    int widx = w & 1023;
    int wh   = widx >> 5;
    int ww   = widx & 31;
    int r    = t >> 3;
    int c    = t & 7;
    int h    = (wh * 8 + r + 4) & 255;
    int wc   = (ww * 8 + c + 4) & 255;
    return (b << 16) | (h << 8) | wc;
}

__device__ __forceinline__ uint32_t smem_to_u32(const void* p) {
    uint32_t a;
    asm("{ .reg .u64 t; cvta.to.shared.u64 t, %1; cvt.u32.u64 %0, t; }" : "=r"(a) : "l"(p));
    return a;
}

#define CP_ASYNC16(dst, src) \
    asm volatile("cp.async.cg.shared.global [%0], [%1], 16;" :: "r"(dst), "l"(src))
#define CP_COMMIT() asm volatile("cp.async.commit_group;")
#define CP_WAIT(n)  asm volatile("cp.async.wait_group %0;" :: "n"(n))

#define LDM_X4(r0, r1, r2, r3, addr) \
    asm volatile("ldmatrix.sync.aligned.m8n8.x4.shared.b16 {%0,%1,%2,%3}, [%4];" \
                 : "=r"(r0), "=r"(r1), "=r"(r2), "=r"(r3) : "r"(addr))
#define LDM_X4_T(r0, r1, r2, r3, addr) \
    asm volatile("ldmatrix.sync.aligned.m8n8.x4.trans.shared.b16 {%0,%1,%2,%3}, [%4];" \
                 : "=r"(r0), "=r"(r1), "=r"(r2), "=r"(r3) : "r"(addr))

#define MMA_F16(d, a, b) \
    asm volatile("mma.sync.aligned.m16n8k16.row.col.f32.f16.f16.f32 " \
                 "{%0,%1,%2,%3}, {%4,%5,%6,%7}, {%8,%9}, {%0,%1,%2,%3};" \
                 : "+f"((d)[0]), "+f"((d)[1]), "+f"((d)[2]), "+f"((d)[3]) \
                 : "r"((a)[0]), "r"((a)[1]), "r"((a)[2]), "r"((a)[3]), \
                   "r"((b)[0]), "r"((b)[1]))

__device__ __forceinline__ uint32_t pk_h2(float x, float y) {
    __half2 t = __floats2half2_rn(x, y);
    return *(uint32_t*)&t;
}
__device__ __forceinline__ float ex2f(float x) {
    float y;
    asm("ex2.approx.ftz.f32 %0, %1;" : "=f"(y) : "f"(x));
    return y;
}

// ---------------------------------------------------------------------------
// Prep kernels
// ---------------------------------------------------------------------------
// Fused: x conversion (12,582,912 items) + qkv weight conversion (27,648).
__global__ __launch_bounds__(256) void prep_x_wq(
    const float* __restrict__ x, const float* __restrict__ qkv_w,
    uint32_t* __restrict__ xo, uint32_t* __restrict__ wq)
{
    int idx = blockIdx.x * 256 + threadIdx.x;
    if (idx < 12582912) {
        int m = idx / 48, c4 = idx % 48;
        float4 v = *(const float4*)(x + (size_t)map_row(m) * C_DIM + c4 * 4);
        *(uint2*)(xo + ((size_t)m * C_DIM + c4 * 4) / 2) =
            make_uint2(pk_h2(v.x, v.y), pk_h2(v.z, v.w));
    } else {
        int it = idx - 12582912;                       // 27648 items
        int row = it / 48, c4 = it % 48;
        float4 v = *(const float4*)(qkv_w + (size_t)row * C_DIM + c4 * 4);
        *(uint2*)(wq + ((size_t)row * C_DIM + c4 * 4) / 2) =
            make_uint2(pk_h2(v.x, v.y), pk_h2(v.z, v.w));
    }
}

// Combined fp16 bias: biasc[wc][h][t][j] = rpb_table[rel_idx[t*64+j]*NH+h] + mask[wc][t*64+j]
// One half2 per thread; 12,582,912 half2 items.
__global__ __launch_bounds__(256) void prep_biasc(
    const float* __restrict__ rpb_table, const int* __restrict__ rel_idx,
    const float* __restrict__ mask, uint32_t* __restrict__ biasc)
{
    int p2 = blockIdx.x * 256 + threadIdx.x;
    int tj2  = p2 & 2047;
    int rest = p2 >> 11;
    int hh = rest % NH;
    int wc = rest / NH;
    int tj = tj2 * 2;
    float v0 = rpb_table[rel_idx[tj]     * NH + hh] + mask[(size_t)wc * 4096 + tj];
    float v1 = rpb_table[rel_idx[tj + 1] * NH + hh] + mask[(size_t)wc * 4096 + tj + 1];
    biasc[(size_t)p2] = pk_h2(v0, v1);
}

// Remaining weights: wp (9216) | w1 (36864) | w2 (36864) = 82944 items.
__device__ __forceinline__ void cvt_w(const float* w, uint32_t* wo, int item, int K) {
    int k4 = K / 4;
    int row = item / k4, c4 = item % k4;
    float4 v = *(const float4*)(w + (size_t)row * K + c4 * 4);
    *(uint2*)(wo + ((size_t)row * K + c4 * 4) / 2) =
        make_uint2(pk_h2(v.x, v.y), pk_h2(v.z, v.w));
}
__global__ __launch_bounds__(256) void prep_rest(
    const float* __restrict__ proj_w, const float* __restrict__ fc1w,
    const float* __restrict__ fc2w,
    uint32_t* __restrict__ wp, uint32_t* __restrict__ w1, uint32_t* __restrict__ w2)
{
    int idx = blockIdx.x * 256 + threadIdx.x;
    if (idx < 9216)        cvt_w(proj_w, wp, idx,         C_DIM);
    else if (idx < 46080)  cvt_w(fc1w,   w1, idx - 9216,  C_DIM);
    else if (idx < 82944)  cvt_w(fc2w,   w2, idx - 46080, HIDDEN);
}

// ---------------------------------------------------------------------------
// Pipelined fp16 HMMA GEMM (R13 config — best measured).
// ---------------------------------------------------------------------------
#define BM   256
#define BK   64
#define RS   144
#define ATB  (256 * RS)
#define BTB  (64 * RS)
#define SSTG (ATB + BTB)
#define MMSMEM (2 * SSTG)

template<bool SCATTER, bool DOGELU>
__global__ __launch_bounds__(256, 2) void mm_f16(
    const __half* __restrict__ A, const __half* __restrict__ W,
    const float* __restrict__ bias, uint32_t* __restrict__ Ou,
    float* __restrict__ Of, int N, int K)
{
    extern __shared__ char sm[];
    const uint32_t sbase = smem_to_u32(sm);

    const int tid = threadIdx.x, wid = tid >> 5, lane = tid & 31;
    const int warpM = wid & 3, warpN = wid >> 2;
    const int rowBase = blockIdx.y * BM;
    const int colBase = blockIdx.x * 64;
    const int nch = K / BK;

    const __half* aSrc0 = A + (size_t)(rowBase + (tid >> 3)) * K + (tid & 7) * 8;
    const __half* bSrc0 = W + (size_t)(colBase + (tid >> 3)) * K + (tid & 7) * 8;
    const uint32_t dDst0 = (tid >> 3) * RS + (tid & 7) * 16;
    const size_t aStep = (size_t)32 * K;

    auto issue = [&](int s, int it) {
        uint32_t sb = sbase + s * SSTG;
        int k0 = it * BK;
        #pragma unroll
        for (int t = 0; t < 8; t++)
            CP_ASYNC16(sb + dDst0 + t * (32 * RS), aSrc0 + k0 + t * aStep);
        #pragma unroll
        for (int t = 0; t < 2; t++)
            CP_ASYNC16(sb + ATB + dDst0 + t * (32 * RS), bSrc0 + k0 + t * aStep);
        CP_COMMIT();
    };

    const uint32_t aRowL = (uint32_t)(warpM * 64 + (lane & 15));
    const uint32_t aColB = (uint32_t)((lane >> 4) * 16);
    const uint32_t bRowL = (uint32_t)(warpN * 32 + (lane & 7) + ((lane >> 4) << 3));
    const uint32_t bColB = (uint32_t)(((lane >> 3) & 1) * 16);

    float acc[4][4][4] = {};

    issue(0, 0);

    for (int it = 0; it < nch; it++) {
        CP_WAIT(0);
        __syncthreads();
        if (it + 1 < nch) issue((it + 1) & 1, it + 1);

        const uint32_t stg = sbase + (it & 1) * SSTG;
        #pragma unroll
        for (int kk = 0; kk < BK; kk += 16) {
            uint32_t ah[4][4], bb[2][4];
            #pragma unroll
            for (int mt = 0; mt < 4; mt++) {
                uint32_t off = (aRowL + mt * 16) * RS + aColB + kk * 2;
                LDM_X4(ah[mt][0], ah[mt][1], ah[mt][2], ah[mt][3], stg + off);
            }
            #pragma unroll
            for (int nt2 = 0; nt2 < 2; nt2++) {
                uint32_t off = ATB + (bRowL + nt2 * 16) * RS + bColB + kk * 2;
                LDM_X4(bb[nt2][0], bb[nt2][1], bb[nt2][2], bb[nt2][3], stg + off);
            }
            #pragma unroll
            for (int mt = 0; mt < 4; mt++) {
                #pragma unroll
                for (int n = 0; n < 4; n++) {
                    uint32_t bf[2] = { bb[n >> 1][(n & 1) * 2], bb[n >> 1][(n & 1) * 2 + 1] };
                    MMA_F16(acc[mt][n], ah[mt], bf);
                }
            }
        }
    }

    const int qid = lane >> 2;
    const int cid2 = (lane & 3) * 2;
    #pragma unroll
    for (int mt = 0; mt < 4; mt++) {
        #pragma unroll
        for (int hf = 0; hf < 2; hf++) {
            int row = rowBase + warpM * 64 + mt * 16 + qid + hf * 8;
            if (SCATTER) row = map_row(row);
            #pragma unroll
            for (int n = 0; n < 4; n++) {
                int col = colBase + warpN * 32 + n * 8 + cid2;
                float2 bv = *(const float2*)(bias + col);
                float ox = acc[mt][n][hf * 2 + 0] + bv.x;
                float oy = acc[mt][n][hf * 2 + 1] + bv.y;
                if (DOGELU) {
                    ox = 0.5f * ox * (1.0f + erff(ox * 0.70710678118654752f));
                    oy = 0.5f * oy * (1.0f + erff(oy * 0.70710678118654752f));
                }
                if (Ou) *(uint32_t*)(Ou + ((size_t)row * N + col) / 2) = pk_h2(ox, oy);
                else    *(float2*)(Of + (size_t)row * N + col) = make_float2(ox, oy);
            }
        }
    }
}

// ---------------------------------------------------------------------------
// Tensor-core attention v3: warp = 16 query rows, 4 warps per (window,head)
// unit, 2 units per 256-thr CTA. Combined fp16 bias stream.
//   smem: 2 units x (Q,K,V 64x32 @80B) = 30720 B.
// ---------------------------------------------------------------------------
#define AT_SMEM 30720

__global__ __launch_bounds__(256, 2) void attn_mma(
    const __half* __restrict__ qkv, const uint32_t* __restrict__ biasc,
    uint32_t* __restrict__ outp)
{
    extern __shared__ char smraw[];
    const uint32_t sbase = smem_to_u32(smraw);
    const int tid = threadIdx.x, wid = tid >> 5, lane = tid & 31;
    const int u  = wid >> 2;            // unit within CTA (0,1)
    const int wq = wid & 3;             // 16-row q tile within unit
    const int wh = blockIdx.x * 2 + u;
    const int w  = wh / NH;
    const int hh = wh - w * NH;
    const size_t rowbase = (size_t)w * 64;

    const uint32_t Qs = sbase + u * 15360;
    const uint32_t Ks = Qs + 5120;
    const uint32_t Vs = Qs + 10240;

    // ---- load Q,K,V tiles (64x32 half each): 128 thr/unit, 2 chunks/tile ----
    {
        int tt = (wid & 3) * 32 + lane;            // 0..127 within unit
        const __half* base = qkv + rowbase * QKV_N + hh * 32;
        #pragma unroll
        for (int i = 0; i < 2; i++) {
            int c = tt + i * 128;                  // 0..255
            int row = c >> 2, seg = c & 3;
            const __half* src = base + (size_t)row * QKV_N + seg * 8;
            uint32_t d = row * 80 + seg * 16;
            CP_ASYNC16(Qs + d, src);
            CP_ASYNC16(Ks + d, src + 192);
            CP_ASYNC16(Vs + d, src + 384);
        }
        CP_COMMIT();
    }
    CP_WAIT(0);
    __syncthreads();

    const int qid = lane >> 2, cid = lane & 3;

    // ---- QK^T: s[n][4] over 8 col-tiles, rows wq*16..+16 ----
    const uint32_t aRow  = (uint32_t)(wq * 16 + (lane & 15));
    const uint32_t aColB = (uint32_t)((lane >> 4) * 16);
    const uint32_t bRow  = (uint32_t)((lane & 7) + ((lane >> 4) << 3));
    const uint32_t bColB = (uint32_t)(((lane >> 3) & 1) * 16);

    float s[8][4] = {};
    #pragma unroll
    for (int ks = 0; ks < 2; ks++) {
        uint32_t qf[4];
        LDM_X4(qf[0], qf[1], qf[2], qf[3], Qs + aRow * 80 + aColB + ks * 32);
        #pragma unroll
        for (int p = 0; p < 4; p++) {
            uint32_t kb[4];
            LDM_X4(kb[0], kb[1], kb[2], kb[3],
                   Ks + (bRow + p * 16) * 80 + bColB + ks * 32);
            #pragma unroll
            for (int nn = 0; nn < 2; nn++) {
                uint32_t bf[2] = { kb[nn * 2], kb[nn * 2 + 1] };
                MMA_F16(s[p * 2 + nn], qf, bf);
            }
        }
    }

    // ---- combined bias (fp16) + softmax (ex2) ----
    const int t0 = wq * 16 + qid;
    const int t1 = t0 + 8;
    const uint32_t* brow = biasc + ((size_t)(w & 1023) * NH + hh) * 2048;
    float mx0 = -1e30f, mx1 = -1e30f;
    #pragma unroll
    for (int n = 0; n < 8; n++) {
        __half2 b0 = *(const __half2*)(brow + t0 * 32 + n * 4 + cid);
        __half2 b1 = *(const __half2*)(brow + t1 * 32 + n * 4 + cid);
        float2 f0 = __half22float2(b0);
        float2 f1 = __half22float2(b1);
        s[n][0] = fmaf(s[n][0], SCALE_F, f0.x);
        s[n][1] = fmaf(s[n][1], SCALE_F, f0.y);
        s[n][2] = fmaf(s[n][2], SCALE_F, f1.x);
        s[n][3] = fmaf(s[n][3], SCALE_F, f1.y);
        mx0 = fmaxf(mx0, fmaxf(s[n][0], s[n][1]));
        mx1 = fmaxf(mx1, fmaxf(s[n][2], s[n][3]));
    }
    mx0 = fmaxf(mx0, __shfl_xor_sync(0xffffffffu, mx0, 1));
    mx0 = fmaxf(mx0, __shfl_xor_sync(0xffffffffu, mx0, 2));
    mx1 = fmaxf(mx1, __shfl_xor_sync(0xffffffffu, mx1, 1));
    mx1 = fmaxf(mx1, __shfl_xor_sync(0xffffffffu, mx1, 2));

    float sm0 = 0.f, sm1 = 0.f;
    #pragma unroll
    for (int n = 0; n < 8; n++) {
        s[n][0] = ex2f((s[n][0] - mx0) * L2E_F);
        s[n][1] = ex2f((s[n][1] - mx0) * L2E_F);
        s[n][2] = ex2f((s[n][2] - mx1) * L2E_F);
        s[n][3] = ex2f((s[n][3] - mx1) * L2E_F);
        sm0 += s[n][0] + s[n][1];
        sm1 += s[n][2] + s[n][3];
    }
    sm0 += __shfl_xor_sync(0xffffffffu, sm0, 1);
    sm0 += __shfl_xor_sync(0xffffffffu, sm0, 2);
    sm1 += __shfl_xor_sync(0xffffffffu, sm1, 1);
    sm1 += __shfl_xor_sync(0xffffffffu, sm1, 2);
    const float inva = 1.f / sm0;
    const float invb = 1.f / sm1;

    // pack probs -> fp16 A-fragments: pf[k2][4]
    uint32_t pf[4][4];
    #pragma unroll
    for (int k2 = 0; k2 < 4; k2++) {
        pf[k2][0] = pk_h2(s[2 * k2][0],     s[2 * k2][1]);
        pf[k2][1] = pk_h2(s[2 * k2][2],     s[2 * k2][3]);
        pf[k2][2] = pk_h2(s[2 * k2 + 1][0], s[2 * k2 + 1][1]);
        pf[k2][3] = pk_h2(s[2 * k2 + 1][2], s[2 * k2 + 1][3]);
    }

    // ---- PV: o[nt][4], V via ldmatrix.trans ----
    float o[4][4] = {};
    const uint32_t vRow  = (uint32_t)(lane & 15);
    const uint32_t vColB = (uint32_t)((lane >> 4) * 16);
    #pragma unroll
    for (int k2 = 0; k2 < 4; k2++) {
        #pragma unroll
        for (int p = 0; p < 2; p++) {
            uint32_t vb[4];
            LDM_X4_T(vb[0], vb[1], vb[2], vb[3],
                     Vs + (k2 * 16 + vRow) * 80 + vColB + p * 32);
            #pragma unroll
            for (int nn = 0; nn < 2; nn++) {
                uint32_t bf[2] = { vb[nn * 2], vb[nn * 2 + 1] };
                MMA_F16(o[p * 2 + nn], pf[k2], bf);
            }
        }
    }

    // ---- normalize + store fp16 pairs ----
    uint32_t* o0 = outp + ((rowbase + t0) * C_DIM + hh * 32) / 2;
    uint32_t* o1 = outp + ((rowbase + t1) * C_DIM + hh * 32) / 2;
    #pragma unroll
    for (int nt = 0; nt < 4; nt++) {
        int c2 = (nt * 8 + cid * 2) >> 1;
        o0[c2] = pk_h2(o[nt][0] * inva, o[nt][1] * inva);
        o1[c2] = pk_h2(o[nt][2] * invb, o[nt][3] * invb);
    }
}

// ---------------------------------------------------------------------------
// LN kernels (unchanged)
// ---------------------------------------------------------------------------
__global__ __launch_bounds__(256) void ln1_k(
    const float* __restrict__ y, const float* __restrict__ resx,
    const float* __restrict__ g, const float* __restrict__ b,
    float* __restrict__ of, uint32_t* __restrict__ oh)
{
    const size_t token = (size_t)blockIdx.x * 8 + (threadIdx.x >> 5);
    const int lane = threadIdx.x & 31;
    const size_t yb = token * C_DIM;

    float v[6];
    float sum = 0.f;
    #pragma unroll
    for (int i = 0; i < 6; i++) { v[i] = y[yb + lane + 32 * i]; sum += v[i]; }
    #pragma unroll
    for (int o = 16; o; o >>= 1) sum += __shfl_xor_sync(0xffffffffu, sum, o);
    const float mu = sum * (1.f / 192.f);
    float sq = 0.f;
    #pragma unroll
    for (int i = 0; i < 6; i++) { float d = v[i] - mu; sq = fmaf(d, d, sq); }
    #pragma unroll
    for (int o = 16; o; o >>= 1) sq += __shfl_xor_sync(0xffffffffu, sq, o);
    const float inv = rsqrtf(sq * (1.f / 192.f) + 1e-5f);

    #pragma unroll
    for (int i = 0; i < 6; i++) {
        int c = lane + 32 * i;
        float r = resx[yb + c] + (v[i] - mu) * inv * g[c] + b[c];
        of[yb + c] = r;
        ((__half*)oh)[yb + c] = __float2half_rn(r);
    }
}

__global__ __launch_bounds__(256) void ln2_k(
    const float* __restrict__ y, const float* __restrict__ r,
    const float* __restrict__ g, const float* __restrict__ b,
    float* __restrict__ outp)
{
    const size_t token = (size_t)blockIdx.x * 8 + (threadIdx.x >> 5);
    const int lane = threadIdx.x & 31;
    const size_t yb = token * C_DIM;

    float v[6];
    float sum = 0.f;
    #pragma unroll
    for (int i = 0; i < 6; i++) { v[i] = y[yb + lane + 32 * i]; sum += v[i]; }
    #pragma unroll
    for (int o = 16; o; o >>= 1) sum += __shfl_xor_sync(0xffffffffu, sum, o);
    const float mu = sum * (1.f / 192.f);
    float sq = 0.f;
    #pragma unroll
    for (int i = 0; i < 6; i++) { float d = v[i] - mu; sq = fmaf(d, d, sq); }
    #pragma unroll
    for (int o = 16; o; o >>= 1) sq += __shfl_xor_sync(0xffffffffu, sq, o);
    const float inv = rsqrtf(sq * (1.f / 192.f) + 1e-5f);

    #pragma unroll
    for (int i = 0; i < 6; i++) {
        int c = lane + 32 * i;
        outp[yb + c] = r[yb + c] + (v[i] - mu) * inv * g[c] + b[c];
    }
}

// ---------------------------------------------------------------------------
// Launch (attention at capture slot 4)
// ---------------------------------------------------------------------------
extern "C" void kernel_launch(void* const* d_in, const int* in_sizes, int n_in,
                              void* d_out, int out_size)
{
    const float* x      = (const float*)d_in[0];
    const float* mask   = (const float*)d_in[1];
    const int*   relidx = (const int*)  d_in[2];
    const float* qkv_w  = (const float*)d_in[3];
    const float* qkv_b  = (const float*)d_in[4];
    const float* proj_w = (const float*)d_in[5];
    const float* proj_b = (const float*)d_in[6];
    const float* rpb    = (const float*)d_in[7];
    const float* n1g    = (const float*)d_in[8];
    const float* n1b    = (const float*)d_in[9];
    const float* n2g    = (const float*)d_in[10];
    const float* n2b    = (const float*)d_in[11];
    const float* fc1w   = (const float*)d_in[12];
    const float* fc1b   = (const float*)d_in[13];
    const float* fc2w   = (const float*)d_in[14];
    const float* fc2b   = (const float*)d_in[15];
    float* out = (float*)d_out;

    char* pool;
    cudaGetSymbolAddress((void**)&pool, g_pool);
    __half*   q   = (__half*)(pool);
    __half*   h   = (__half*)(pool);
    __half*   xb  = (__half*)(pool + OFF_XA);
    __half*   a   = (__half*)(pool + OFF_XA);
    float*    tb  = (float*)(pool + OFF_T);
    float*    x1f = (float*)(pool + OFF_X1F);
    uint32_t* x1h = (uint32_t*)(pool + OFF_X1H);

    __half *wq, *wp, *w1, *w2, *biasc;
    cudaGetSymbolAddress((void**)&wq, g_wq);
    cudaGetSymbolAddress((void**)&wp, g_wp);
    cudaGetSymbolAddress((void**)&w1, g_w1);
    cudaGetSymbolAddress((void**)&w2, g_w2);
    cudaGetSymbolAddress((void**)&biasc, g_biasc);

    cudaFuncSetAttribute(mm_f16<false, false>, cudaFuncAttributeMaxDynamicSharedMemorySize, MMSMEM);
    cudaFuncSetAttribute(mm_f16<true,  false>, cudaFuncAttributeMaxDynamicSharedMemorySize, MMSMEM);
    cudaFuncSetAttribute(mm_f16<false, true >, cudaFuncAttributeMaxDynamicSharedMemorySize, MMSMEM);
    cudaFuncSetAttribute(attn_mma, cudaFuncAttributeMaxDynamicSharedMemorySize, AT_SMEM);

    // 1. x + qkv weights -> fp16
    prep_x_wq<<<12610560 / 256, 256>>>(x, qkv_w, (uint32_t*)xb, (uint32_t*)wq);
    // 2. combined fp16 bias (rpb + mask)
    prep_biasc<<<12582912 / 256, 256>>>(rpb, relidx, mask, (uint32_t*)biasc);
    // 3. qkv GEMM
    mm_f16<false, false><<<dim3(QKV_N / 64, M_TOT / BM), 256, MMSMEM>>>(
        xb, wq, qkv_b, (uint32_t*)q, nullptr, QKV_N, C_DIM);
    // 4. attention (capture slot)
    attn_mma<<<NWIN * NH / 2, 256, AT_SMEM>>>(q, (const uint32_t*)biasc, (uint32_t*)a);
    // 5. remaining weight preps
    prep_rest<<<82944 / 256, 256>>>(proj_w, fc1w, fc2w,
                                    (uint32_t*)wp, (uint32_t*)w1, (uint32_t*)w2);
    // 6. proj GEMM + scatter, fp32 out
    mm_f16<true, false><<<dim3(C_DIM / 64, M_TOT / BM), 256, MMSMEM>>>(
        a, wp, proj_b, nullptr, tb, C_DIM, C_DIM);
    // 7. LN1
    ln1_k<<<M_TOT / 8, 256>>>(tb, x, n1g, n1b, x1f, x1h);
    // 8. fc1 + GELU
    mm_f16<false, true><<<dim3(HIDDEN / 64, M_TOT / BM), 256, MMSMEM>>>(
        (const __half*)x1h, w1, fc1b, (uint32_t*)h, nullptr, HIDDEN, C_DIM);
    // 9. fc2
    mm_f16<false, false><<<dim3(C_DIM / 64, M_TOT / BM), 256, MMSMEM>>>(
        h, w2, fc2b, nullptr, tb, C_DIM, HIDDEN);
    // 10. LN2 -> out
    ln2_k<<<M_TOT / 8, 256>>>(tb, x1f, n2g, n2b, out);
}